// round 10
// baseline (speedup 1.0000x reference)
#include <cuda_runtime.h>
#include <math.h>

// Problem constants
#define NB 64
#define NF 36
#define NQ 100
#define NQP 101                         // auction smem stride (conflict-free)
#define NT 20
#define NC 92
#define NQUERY (NB * NF * NQ)          // 230400
#define NINST  (NB * NF)               // 2304
#define COST_ELEMS (NQUERY * NT)       // 4608000
#define IDX_ELEMS  (NINST * NT)        // 46080
#define FULLW 0xffffffffu

// ---------------------------------------------------------------------------
// Kernel A: cost tensor, chunked-staging version.
// Block = one (b,f) frame. 4 chunks of 32 logit rows are staged via perfectly
// contiguous float4 copies (4 wavefronts/instr); warp c then computes queries
// 32c..32c+31 from smem. Same arithmetic as the R7 kernel.
// ---------------------------------------------------------------------------
__global__ __launch_bounds__(128) void cost_kernel(
        const float* __restrict__ logits,
        const float* __restrict__ pboxes,
        const int*   __restrict__ tlabels,
        const float* __restrict__ tboxes,
        float* __restrict__ cost)
{
    const int inst = blockIdx.x;          // b*36 + f
    const int b = inst / NF;
    const int f = inst - b * NF;
    const int tid = threadIdx.x;

    __shared__ float4 schunk[32 * 23];    // 11.75 KB: 32 logit rows
    __shared__ float  sout[NQ * 21];      // 8.4 KB output staging
    __shared__ float4 stbc[NT];           // target cxcywh
    __shared__ float4 stbx[NT];           // target xyxy
    __shared__ float  sarea[NT];
    __shared__ int    slab[NT];

    if (tid < NT) {
        const size_t tb_ = (size_t)(f * NB + b) * NT + tid;
        const float4 tb = ((const float4*)tboxes)[tb_];
        stbc[tid] = tb;
        const float x0 = tb.x - 0.5f * tb.z, y0 = tb.y - 0.5f * tb.w;
        const float x1 = tb.x + 0.5f * tb.z, y1 = tb.y + 0.5f * tb.w;
        stbx[tid]  = make_float4(x0, y0, x1, y1);
        sarea[tid] = (x1 - x0) * (y1 - y0);
        slab[tid]  = tlabels[tb_];
    }
    __syncthreads();

    const float4* lg4 = (const float4*)(logits + ((size_t)b * (NF * NQ) + f * NQ) * NC);

    #pragma unroll
    for (int c = 0; c < 4; ++c) {
        const int qbase = c * 32;
        const int nrows = (qbase + 32 <= NQ) ? 32 : (NQ - qbase);
        const int nf4 = nrows * 23;

        // contiguous coalesced copy: smem layout == gmem layout (stride 23 f4)
        for (int i = tid; i < nf4; i += 128)
            schunk[i] = lg4[qbase * 23 + i];
        __syncthreads();

        const int r = tid - qbase;        // warp c handles this chunk
        if (r >= 0 && r < nrows) {
            const int q = tid;
            const float* row = (const float*)&schunk[r * 23];

            // softmax denominator from smem (vector LDS, conflict-free: 23 odd)
            float s = 0.0f;
            #pragma unroll
            for (int i = 0; i < 23; ++i) {
                const float4 v = schunk[r * 23 + i];
                s += (__expf(v.x) + __expf(v.y)) + (__expf(v.z) + __expf(v.w));
            }
            const float rs = __fdividef(1.0f, s);

            const float4 pb = *(const float4*)(pboxes
                              + ((size_t)b * (NF * NQ) + f * NQ + q) * 4);
            const float px0 = pb.x - 0.5f * pb.z;
            const float py0 = pb.y - 0.5f * pb.w;
            const float px1 = pb.x + 0.5f * pb.z;
            const float py1 = pb.y + 0.5f * pb.w;
            const float area1 = (px1 - px0) * (py1 - py0);

            #pragma unroll
            for (int t = 0; t < NT; ++t) {
                const float prob = __expf(row[slab[t]]) * rs;   // LDS gather

                const float4 tc = stbc[t];
                const float l1 = fabsf(pb.x - tc.x) + fabsf(pb.y - tc.y)
                               + fabsf(pb.z - tc.z) + fabsf(pb.w - tc.w);

                const float4 tx = stbx[t];
                const float ltx = fmaxf(px0, tx.x), lty = fmaxf(py0, tx.y);
                const float rbx = fminf(px1, tx.z), rby = fminf(py1, tx.w);
                const float iw = fmaxf(rbx - ltx, 0.0f), ih = fmaxf(rby - lty, 0.0f);
                const float inter = iw * ih;
                const float uni = area1 + sarea[t] - inter;

                const float elx = fminf(px0, tx.x), ely = fminf(py0, tx.y);
                const float erx = fmaxf(px1, tx.z), ery = fmaxf(py1, tx.w);
                const float ew = fmaxf(erx - elx, 0.0f), eh = fmaxf(ery - ely, 0.0f);
                const float areae = ew * eh;

                const float giou = __fdividef(inter * areae - uni * (areae - uni),
                                              uni * areae);

                sout[q * 21 + t] = -prob + 5.0f * l1 - 2.0f * giou;
            }
        }
        __syncthreads();                  // chunk buffer reuse barrier
    }

    float* cbase = cost + (size_t)inst * (NQ * NT);
    #pragma unroll 4
    for (int i = tid; i < NQ * NT; i += 128) {
        const int q2 = i / NT, t2 = i - q2 * NT;
        cbase[i] = sout[q2 * 21 + t2];
    }
}

// ---------------------------------------------------------------------------
// Kernel B: synchronous Jacobi auction (EXACT R3 version — best: 27.6 us).
// ---------------------------------------------------------------------------
__global__ void auction_kernel(const float* __restrict__ cost,
                               float* __restrict__ out_pred,
                               float* __restrict__ out_tgt)
{
    const int inst = blockIdx.x;
    const int t = threadIdx.x;

    __shared__ float ben[NT * NQP];
    __shared__ float price[NQ];
    __shared__ int   owner[NQ];
    __shared__ int   obj_of[NT];
    __shared__ float sbid[NT];
    __shared__ int   sobj[NT];
    __shared__ int   blist[NT];

    const float* c = cost + (size_t)inst * (NQ * NT);

    float mx = -INFINITY, mn = INFINITY;
    for (int i = t; i < NQ * NT; i += 32) {
        const int qq = i / NT, tt = i - qq * NT;
        const float v = -c[i];
        ben[tt * NQP + qq] = v;
        mx = fmaxf(mx, v);
        mn = fminf(mn, v);
    }
    for (int i = t; i < NQ; i += 32) { price[i] = 0.0f; owner[i] = -1; }
    if (t < NT) obj_of[t] = -1;

    #pragma unroll
    for (int o = 16; o > 0; o >>= 1) {
        mx = fmaxf(mx, __shfl_xor_sync(FULLW, mx, o));
        mn = fminf(mn, __shfl_xor_sync(FULLW, mn, o));
    }
    const float eps = (mx - mn + 1e-06f) / 1000.0f;
    __syncwarp();

    for (int it = 0; it < 20000; ++it) {
        const bool un = (t < NT) && (obj_of[t] < 0);
        const unsigned mask = __ballot_sync(FULLW, un);
        if (!mask) break;
        const int u = __popc(mask);

        if (un) blist[__popc(mask & ((1u << t) - 1u))] = t;
        __syncwarp();

        const int gp = 32 / u;
        const int gsize = 1 << (31 - __clz(gp));
        const int grp = t / gsize;
        const int lig = t - grp * gsize;
        const bool live = (grp < u);
        const int t2 = blist[live ? grp : 0];

        float b1 = -INFINITY, b2 = -INFINITY;
        int i1 = 0;
        const float* br = &ben[t2 * NQP];
        for (int q = lig; q < NQ; q += gsize) {
            const float v = br[q] - price[q];
            if (v > b1) { b2 = b1; b1 = v; i1 = q; }
            else if (v > b2) { b2 = v; }
        }
        for (int o = gsize >> 1; o > 0; o >>= 1) {
            const float ob1 = __shfl_xor_sync(FULLW, b1, o);
            const int   oi1 = __shfl_xor_sync(FULLW, i1, o);
            const float ob2 = __shfl_xor_sync(FULLW, b2, o);
            const bool aw = (b1 > ob1) || (b1 == ob1 && i1 < oi1);
            const float lose = aw ? ob1 : b1;
            b2 = fmaxf(lose, fmaxf(b2, ob2));
            b1 = aw ? b1 : ob1;
            i1 = aw ? i1 : oi1;
        }
        if (live && lig == 0) {
            sbid[t2] = price[i1] + (b1 - b2) + eps;
            sobj[t2] = i1;
        }
        __syncwarp();

        bool winf = false;
        int myq = -1;
        if (un) {
            myq = sobj[t];
            const float mybid = sbid[t];
            winf = true;
            for (unsigned mm = mask & ~(1u << t); mm; mm &= mm - 1u) {
                const int t3 = __ffs(mm) - 1;
                if (sobj[t3] == myq) {
                    const float ob = sbid[t3];
                    if (ob > mybid || (ob == mybid && t3 < t)) winf = false;
                }
            }
        }
        __syncwarp();

        int old = -1;
        if (winf) old = owner[myq];
        __syncwarp();
        if (winf && old >= 0) obj_of[old] = -1;
        __syncwarp();
        if (winf) {
            obj_of[t] = myq;
            price[myq] = sbid[t];
            owner[myq] = t;
        }
        __syncwarp();
    }

    if (t < NT) {
        const int v = obj_of[t];
        int rank = 0;
        #pragma unroll
        for (int t3 = 0; t3 < NT; ++t3) {
            const int v2 = obj_of[t3];
            rank += (v2 < v) || (v2 == v && t3 < t);
        }
        out_pred[(size_t)inst * NT + rank] = (float)v;
        out_tgt [(size_t)inst * NT + rank] = (float)t;
    }
}

// ---------------------------------------------------------------------------
extern "C" void kernel_launch(void* const* d_in, const int* in_sizes, int n_in,
                              void* d_out, int out_size)
{
    const float* logits  = (const float*)d_in[0];  // (64, 3600, 92)
    const float* pboxes  = (const float*)d_in[1];  // (64, 3600, 4)
    const int*   tlabels = (const int*)  d_in[2];  // (36, 64, 20)
    const float* tboxes  = (const float*)d_in[3];  // (36, 64, 20, 4)

    float* out  = (float*)d_out;
    float* cost = out;
    float* pidx = out + COST_ELEMS;
    float* tidx = out + COST_ELEMS + IDX_ELEMS;

    cost_kernel<<<NINST, 128>>>(logits, pboxes, tlabels, tboxes, cost);
    auction_kernel<<<NINST, 32>>>(cost, pidx, tidx);
}

// round 11
// speedup vs baseline: 1.3500x; 1.3500x over previous
#include <cuda_runtime.h>
#include <math.h>

// Problem constants
#define NB 64
#define NF 36
#define NQ 100
#define NT 20
#define NC 92
#define NQUERY (NB * NF * NQ)          // 230400
#define NINST  (NB * NF)               // 2304
#define COST_ELEMS (NQUERY * NT)       // 4608000
#define IDX_ELEMS  (NINST * NT)        // 46080
#define FULLW 0xffffffffu

// ---------------------------------------------------------------------------
// Fused kernel, ~10 KB smem. Block = one (b,f) instance, 128 threads.
//   Phase A: R7 cost body (direct per-thread row reads) -> sout (stride 21),
//            block-reduced benefit max/min, coalesced cost store.
//   Phase B: warps 1-3 exit; warp 0 runs the R3 auction reading benefit
//            straight from sout (ben[t][q] = -sout[q*21+t], conflict-free).
// ---------------------------------------------------------------------------
__global__ __launch_bounds__(128) void fused_kernel(
        const float* __restrict__ logits,
        const float* __restrict__ pboxes,
        const int*   __restrict__ tlabels,
        const float* __restrict__ tboxes,
        float* __restrict__ cost,
        float* __restrict__ out_pred,
        float* __restrict__ out_tgt)
{
    const int inst = blockIdx.x;          // b*36 + f
    const int b = inst / NF;
    const int f = inst - b * NF;
    const int tid  = threadIdx.x;
    const int lane = tid & 31;
    const int warp = tid >> 5;

    __shared__ float  sout[NQ * 21];      // cost values, stride 21 (8.4 KB)
    __shared__ float4 stbc[NT];           // target cxcywh
    __shared__ float4 stbx[NT];           // target xyxy
    __shared__ float  sarea[NT];
    __shared__ int    slab[NT];
    __shared__ float  wmx[4], wmn[4];
    // auction state
    __shared__ float  price[NQ];
    __shared__ int    owner[NQ];
    __shared__ int    obj_of[NT];
    __shared__ float  sbid[NT];
    __shared__ int    sobj[NT];
    __shared__ int    blist[NT];

    if (tid < NT) {
        const size_t tb_ = (size_t)(f * NB + b) * NT + tid;
        const float4 tb = ((const float4*)tboxes)[tb_];
        stbc[tid] = tb;
        const float x0 = tb.x - 0.5f * tb.z, y0 = tb.y - 0.5f * tb.w;
        const float x1 = tb.x + 0.5f * tb.z, y1 = tb.y + 0.5f * tb.w;
        stbx[tid]  = make_float4(x0, y0, x1, y1);
        sarea[tid] = (x1 - x0) * (y1 - y0);
        slab[tid]  = tlabels[tb_];
        obj_of[tid] = -1;
    }
    for (int i = tid; i < NQ; i += 128) { price[i] = 0.0f; owner[i] = -1; }
    __syncthreads();

    // --- Phase A: R7 cost body ---
    float mx = -INFINITY, mn = INFINITY;
    const int q = tid;
    if (q < NQ) {
        const float* row = logits + ((size_t)b * (NF * NQ) + f * NQ + q) * NC;
        const float4* r4 = (const float4*)row;

        float s = 0.0f;
        #pragma unroll
        for (int i = 0; i < 23; ++i) {
            const float4 v = r4[i];
            s += (__expf(v.x) + __expf(v.y)) + (__expf(v.z) + __expf(v.w));
        }
        const float rs = __fdividef(1.0f, s);

        const float4 pb = *(const float4*)(pboxes + ((size_t)b * (NF * NQ) + f * NQ + q) * 4);
        const float px0 = pb.x - 0.5f * pb.z;
        const float py0 = pb.y - 0.5f * pb.w;
        const float px1 = pb.x + 0.5f * pb.z;
        const float py1 = pb.y + 0.5f * pb.w;
        const float area1 = (px1 - px0) * (py1 - py0);

        #pragma unroll
        for (int t = 0; t < NT; ++t) {
            const float prob = __expf(__ldg(row + slab[t])) * rs;   // L1 hit

            const float4 tc = stbc[t];
            const float l1 = fabsf(pb.x - tc.x) + fabsf(pb.y - tc.y)
                           + fabsf(pb.z - tc.z) + fabsf(pb.w - tc.w);

            const float4 tx = stbx[t];
            const float ltx = fmaxf(px0, tx.x), lty = fmaxf(py0, tx.y);
            const float rbx = fminf(px1, tx.z), rby = fminf(py1, tx.w);
            const float iw = fmaxf(rbx - ltx, 0.0f), ih = fmaxf(rby - lty, 0.0f);
            const float inter = iw * ih;
            const float uni = area1 + sarea[t] - inter;

            const float elx = fminf(px0, tx.x), ely = fminf(py0, tx.y);
            const float erx = fmaxf(px1, tx.z), ery = fmaxf(py1, tx.w);
            const float ew = fmaxf(erx - elx, 0.0f), eh = fmaxf(ery - ely, 0.0f);
            const float areae = ew * eh;

            const float giou = __fdividef(inter * areae - uni * (areae - uni),
                                          uni * areae);

            const float cv = -prob + 5.0f * l1 - 2.0f * giou;
            sout[q * 21 + t] = cv;
            const float bv = -cv;                 // benefit
            mx = fmaxf(mx, bv);
            mn = fminf(mn, bv);
        }
    }
    #pragma unroll
    for (int o = 16; o > 0; o >>= 1) {
        mx = fmaxf(mx, __shfl_xor_sync(FULLW, mx, o));
        mn = fminf(mn, __shfl_xor_sync(FULLW, mn, o));
    }
    if (lane == 0) { wmx[warp] = mx; wmn[warp] = mn; }
    __syncthreads();

    // coalesced cost store
    float* cbase = cost + (size_t)inst * (NQ * NT);
    #pragma unroll 4
    for (int i = tid; i < NQ * NT; i += 128) {
        const int q2 = i / NT, t2 = i - q2 * NT;
        cbase[i] = sout[q2 * 21 + t2];
    }

    if (warp != 0) return;

    // =======================================================================
    // Phase B: R3 auction on warp 0; benefit read as -sout[q*21+t].
    // =======================================================================
    const int t = lane;
    const float gmx = fmaxf(fmaxf(wmx[0], wmx[1]), fmaxf(wmx[2], wmx[3]));
    const float gmn = fminf(fminf(wmn[0], wmn[1]), fminf(wmn[2], wmn[3]));
    const float eps = (gmx - gmn + 1e-06f) / 1000.0f;
    __syncwarp();

    for (int it = 0; it < 20000; ++it) {
        const bool un = (t < NT) && (obj_of[t] < 0);
        const unsigned mask = __ballot_sync(FULLW, un);
        if (!mask) break;
        const int u = __popc(mask);

        if (un) blist[__popc(mask & ((1u << t) - 1u))] = t;
        __syncwarp();

        const int gp = 32 / u;
        const int gsize = 1 << (31 - __clz(gp));
        const int grp = t / gsize;
        const int lig = t - grp * gsize;
        const bool live = (grp < u);
        const int t2 = blist[live ? grp : 0];

        float b1 = -INFINITY, b2 = -INFINITY;
        int i1 = 0;
        for (int qq = lig; qq < NQ; qq += gsize) {
            const float v = -sout[qq * 21 + t2] - price[qq];
            if (v > b1) { b2 = b1; b1 = v; i1 = qq; }
            else if (v > b2) { b2 = v; }
        }
        for (int o = gsize >> 1; o > 0; o >>= 1) {
            const float ob1 = __shfl_xor_sync(FULLW, b1, o);
            const int   oi1 = __shfl_xor_sync(FULLW, i1, o);
            const float ob2 = __shfl_xor_sync(FULLW, b2, o);
            const bool aw = (b1 > ob1) || (b1 == ob1 && i1 < oi1);
            const float lose = aw ? ob1 : b1;
            b2 = fmaxf(lose, fmaxf(b2, ob2));
            b1 = aw ? b1 : ob1;
            i1 = aw ? i1 : oi1;
        }
        if (live && lig == 0) {
            sbid[t2] = price[i1] + (b1 - b2) + eps;
            sobj[t2] = i1;
        }
        __syncwarp();

        bool winf = false;
        int myq = -1;
        if (un) {
            myq = sobj[t];
            const float mybid = sbid[t];
            winf = true;
            for (unsigned mm = mask & ~(1u << t); mm; mm &= mm - 1u) {
                const int t3 = __ffs(mm) - 1;
                if (sobj[t3] == myq) {
                    const float ob = sbid[t3];
                    if (ob > mybid || (ob == mybid && t3 < t)) winf = false;
                }
            }
        }
        __syncwarp();

        int old = -1;
        if (winf) old = owner[myq];
        __syncwarp();
        if (winf && old >= 0) obj_of[old] = -1;   // evictions first
        __syncwarp();
        if (winf) {
            obj_of[t] = myq;
            price[myq] = sbid[t];
            owner[myq] = t;
        }
        __syncwarp();
    }

    // stable argsort of obj_of
    if (t < NT) {
        const int v = obj_of[t];
        int rank = 0;
        #pragma unroll
        for (int t3 = 0; t3 < NT; ++t3) {
            const int v2 = obj_of[t3];
            rank += (v2 < v) || (v2 == v && t3 < t);
        }
        out_pred[(size_t)inst * NT + rank] = (float)v;
        out_tgt [(size_t)inst * NT + rank] = (float)t;
    }
}

// ---------------------------------------------------------------------------
extern "C" void kernel_launch(void* const* d_in, const int* in_sizes, int n_in,
                              void* d_out, int out_size)
{
    const float* logits  = (const float*)d_in[0];  // (64, 3600, 92)
    const float* pboxes  = (const float*)d_in[1];  // (64, 3600, 4)
    const int*   tlabels = (const int*)  d_in[2];  // (36, 64, 20)
    const float* tboxes  = (const float*)d_in[3];  // (36, 64, 20, 4)

    float* out  = (float*)d_out;
    float* cost = out;
    float* pidx = out + COST_ELEMS;
    float* tidx = out + COST_ELEMS + IDX_ELEMS;

    fused_kernel<<<NINST, 128>>>(logits, pboxes, tlabels, tboxes,
                                 cost, pidx, tidx);
}